// round 12
// baseline (speedup 1.0000x reference)
#include <cuda_runtime.h>
#include <cuda_fp16.h>
#include <math.h>
#include <stdint.h>

// Problem constants
#define QS    512
#define BATCH 8
#define CDIM  1024
#define NHEAD 16
#define HCDIM 64
#define MMEM  1536
#define NTOK  (QS * BATCH)   // 4096

// Scratch (device globals: allocation-guard safe)
__device__ float g_q[NTOK * CDIM];
__device__ float g_k[NTOK * CDIM];
__device__ float g_v[NTOK * CDIM];
__device__ float g_x[NTOK * CDIM];

__device__ __forceinline__ uint32_t f2tf32(float f) {
    uint32_t u;
    asm("cvt.rna.tf32.f32 %0, %1;" : "=r"(u) : "f"(f));
    return u;
}

__device__ __forceinline__ void mma_tf32(float c[4],
    uint32_t a0, uint32_t a1, uint32_t a2, uint32_t a3,
    uint32_t b0, uint32_t b1)
{
    asm volatile(
        "mma.sync.aligned.m16n8k8.row.col.f32.tf32.tf32.f32 "
        "{%0,%1,%2,%3}, {%4,%5,%6,%7}, {%8,%9}, {%0,%1,%2,%3};"
        : "+f"(c[0]), "+f"(c[1]), "+f"(c[2]), "+f"(c[3])
        : "r"(a0), "r"(a1), "r"(a2), "r"(a3), "r"(b0), "r"(b1));
}

__device__ __forceinline__ void mma_f16(float c[4],
    uint32_t a0, uint32_t a1, uint32_t a2, uint32_t a3,
    uint32_t b0, uint32_t b1)
{
    asm volatile(
        "mma.sync.aligned.m16n8k16.row.col.f32.f16.f16.f32 "
        "{%0,%1,%2,%3}, {%4,%5,%6,%7}, {%8,%9}, {%0,%1,%2,%3};"
        : "+f"(c[0]), "+f"(c[1]), "+f"(c[2]), "+f"(c[3])
        : "r"(a0), "r"(a1), "r"(a2), "r"(a3), "r"(b0), "r"(b1));
}

__device__ __forceinline__ void cp16(uint32_t dst, const void* src, int sz) {
    asm volatile("cp.async.cg.shared.global [%0], [%1], 16, %2;"
                 :: "r"(dst), "l"(src), "r"(sz));
}
__device__ __forceinline__ void cp_commit() {
    asm volatile("cp.async.commit_group;");
}
__device__ __forceinline__ void cp_wait0() {
    asm volatile("cp.async.wait_group 0;");
}
__device__ __forceinline__ void cp_wait1() {
    asm volatile("cp.async.wait_group 1;");
}

// ---------------------------------------------------------------------------
// FP16 tensor-core GEMM: out[n][o] = sum_k A[n][k] * W[o][k] + bias[o]
// Block tile 128x128, k-chunk 32, 8 warps (2x4), warp tile 64x32.
// mma.sync.m16n8k16.f16 (f32 accum): 2x K per HMMA vs tf32 k8, same 11-bit
// significand rounding -> same error model, half the mma/LDS count.
// Smem rows = 36 halves (72B): B-frag bank = (18g+tig)%32, all distinct.
// ROUND_OUT: store rna-tf32-rounded values (q/k/v path; exactly preserved
// by the attention kernel's truncating consumption). Out-proj: full fp32.
// ---------------------------------------------------------------------------
template <bool ROUND_OUT>
__global__ __launch_bounds__(256) void gemm_f16_nt_bias(
    const float* __restrict__ A, const float* __restrict__ W,
    const float* __restrict__ bias, float* __restrict__ out)
{
    __shared__ __half As[128 * 36];
    __shared__ __half Ws[128 * 36];

    const int tid  = threadIdx.x;
    const int lane = tid & 31;
    const int warp = tid >> 5;
    const int g    = lane >> 2;
    const int tig  = lane & 3;

    const int wm = (warp >> 2) * 64;
    const int wn = (warp & 3) * 32;

    const int n0 = blockIdx.y << 7;
    const int o0 = blockIdx.x << 7;

    const int lrow = tid >> 3;
    const int lcol = (tid & 7) << 2;   // half-index within 32-half chunk

    float c[4][4][4];
    #pragma unroll
    for (int mi = 0; mi < 4; mi++)
        #pragma unroll
        for (int ni = 0; ni < 4; ni++)
            #pragma unroll
            for (int r = 0; r < 4; r++) c[mi][ni][r] = 0.0f;

    float4 ra[4], rw[4];
    #pragma unroll
    for (int p = 0; p < 4; p++) {
        int r = lrow + (p << 5);
        ra[p] = *(const float4*)(A + (size_t)(n0 + r) * CDIM + lcol);
        rw[p] = *(const float4*)(W + (size_t)(o0 + r) * CDIM + lcol);
    }

    for (int k0 = 0; k0 < CDIM; k0 += 32) {
        #pragma unroll
        for (int p = 0; p < 4; p++) {
            int r = lrow + (p << 5);
            __half2 alo = __floats2half2_rn(ra[p].x, ra[p].y);
            __half2 ahi = __floats2half2_rn(ra[p].z, ra[p].w);
            *(__half2*)(As + r * 36 + lcol)     = alo;
            *(__half2*)(As + r * 36 + lcol + 2) = ahi;
            __half2 wlo = __floats2half2_rn(rw[p].x, rw[p].y);
            __half2 whi = __floats2half2_rn(rw[p].z, rw[p].w);
            *(__half2*)(Ws + r * 36 + lcol)     = wlo;
            *(__half2*)(Ws + r * 36 + lcol + 2) = whi;
        }
        __syncthreads();

        if (k0 + 32 < CDIM) {
            #pragma unroll
            for (int p = 0; p < 4; p++) {
                int r = lrow + (p << 5);
                ra[p] = *(const float4*)(A + (size_t)(n0 + r) * CDIM + k0 + 32 + lcol);
                rw[p] = *(const float4*)(W + (size_t)(o0 + r) * CDIM + k0 + 32 + lcol);
            }
        }

        #pragma unroll
        for (int ks = 0; ks < 2; ks++) {
            const int kk = ks << 4;   // 16 halves per mma
            uint32_t a[4][4], b[4][2];
            #pragma unroll
            for (int mi = 0; mi < 4; mi++) {
                // u32 view: row*18 u32 per row; k pair index = kk/2 + tig
                const uint32_t* ap = (const uint32_t*)As
                    + (wm + (mi << 4) + g) * 18 + (kk >> 1) + tig;
                a[mi][0] = ap[0];            // (row g,    k 2tig..2tig+1)
                a[mi][1] = ap[8 * 18];       // (row g+8)
                a[mi][2] = ap[4];            // (row g,    k+8)
                a[mi][3] = ap[8 * 18 + 4];   // (row g+8,  k+8)
            }
            #pragma unroll
            for (int ni = 0; ni < 4; ni++) {
                const uint32_t* bp = (const uint32_t*)Ws
                    + (wn + (ni << 3) + g) * 18 + (kk >> 1) + tig;
                b[ni][0] = bp[0];
                b[ni][1] = bp[4];
            }
            #pragma unroll
            for (int mi = 0; mi < 4; mi++)
                #pragma unroll
                for (int ni = 0; ni < 4; ni++)
                    mma_f16(c[mi][ni], a[mi][0], a[mi][1], a[mi][2], a[mi][3],
                            b[ni][0], b[ni][1]);
        }
        __syncthreads();
    }

    #pragma unroll
    for (int mi = 0; mi < 4; mi++) {
        int row = n0 + wm + (mi << 4) + g;
        #pragma unroll
        for (int ni = 0; ni < 4; ni++) {
            int col = o0 + wn + (ni << 3) + (tig << 1);
            float b0 = bias[col], b1 = bias[col + 1];
            float r00 = c[mi][ni][0] + b0, r01 = c[mi][ni][1] + b1;
            float r10 = c[mi][ni][2] + b0, r11 = c[mi][ni][3] + b1;
            float2 v0, v1;
            if (ROUND_OUT) {
                v0 = make_float2(__uint_as_float(f2tf32(r00)), __uint_as_float(f2tf32(r01)));
                v1 = make_float2(__uint_as_float(f2tf32(r10)), __uint_as_float(f2tf32(r11)));
            } else {
                v0 = make_float2(r00, r01);
                v1 = make_float2(r10, r11);
            }
            *(float2*)(out + (size_t)row * CDIM + col) = v0;
            *(float2*)(out + (size_t)(row + 8) * CDIM + col) = v1;
        }
    }
}

// ---------------------------------------------------------------------------
// TF32 tensor-core flash attention, 2-stage cp.async pipelined KV gather.
// (Unchanged from round-11 winner: 171.6us measured.)
// ---------------------------------------------------------------------------
#define KSTR 68
#define VSTR 72
#define KV_WORDS (64 * KSTR + 64 * VSTR)   // one stage: 8960 words

__global__ __launch_bounds__(128) void attn_tc_kernel(
    const float* __restrict__ qg, const float* __restrict__ kg,
    const float* __restrict__ vg, const float* __restrict__ memkv,
    const int* __restrict__ memlen, const int* __restrict__ padv,
    const unsigned char* __restrict__ mask, float* __restrict__ xout)
{
    extern __shared__ uint32_t smu[];   // 2 * KV_WORDS = 17920 words = 71680 B
    const uint32_t smem_base = (uint32_t)__cvta_generic_to_shared(smu);

    const int tid  = threadIdx.x;
    const int lane = tid & 31;
    const int warp = tid >> 5;       // 0..3
    const int g    = lane >> 2;      // 0..7
    const int tig  = lane & 3;       // 0..3

    const int s0 = blockIdx.x << 6;
    const int b  = blockIdx.y >> 4;
    const int h  = blockIdx.y & 15;
    const int L  = memlen[b];
    const int P  = padv[b];
    const int Teff = L + P;
    const int qrow0 = warp * 16 + g;

    // ---- Stage Q through smem (buffer 0), then into register fragments ----
    {
        float* Qst = (float*)smu;   // [qi][d] stride 68
        for (int i = tid; i < 1024; i += 128) {
            int qi = i >> 4;
            int dc = (i & 15) << 2;
            float4 qv = *(const float4*)(qg + ((size_t)(s0 + qi) * BATCH + b) * CDIM + h * HCDIM + dc);
            *(float4*)(Qst + qi * KSTR + dc) = qv;
        }
    }
    __syncthreads();

    uint32_t qf[8][4];
    {
        const float* q0 = (const float*)smu + qrow0 * KSTR;
        const float* q8 = q0 + 8 * KSTR;
        #pragma unroll
        for (int ks = 0; ks < 8; ks++) {
            const int kk = ks << 3;
            qf[ks][0] = f2tf32(q0[kk + tig] * 0.125f);
            qf[ks][1] = f2tf32(q8[kk + tig] * 0.125f);
            qf[ks][2] = f2tf32(q0[kk + tig + 4] * 0.125f);
            qf[ks][3] = f2tf32(q8[kk + tig + 4] * 0.125f);
        }
    }
    __syncthreads();  // Q staging consumed before prefetch overwrites buffer 0

    float oacc[8][4];
    #pragma unroll
    for (int ni = 0; ni < 8; ni++)
        #pragma unroll
        for (int r = 0; r < 4; r++) oacc[ni][r] = 0.0f;
    float mrow[2] = { -INFINITY, -INFINITY };
    float lrow[2] = { 0.0f, 0.0f };

    const int ntile = (Teff + 63) >> 6;

    // ---- KV gather into stage buffer via cp.async ----
    auto gather = [&](int kt) {
        const int t0 = kt << 6;
        const uint32_t kbase = smem_base + (uint32_t)((kt & 1) * KV_WORDS) * 4u;
        const uint32_t vbase = kbase + 64 * KSTR * 4u;
        for (int i = tid; i < 1024; i += 128) {
            int kj = i >> 4;
            int dc = (i & 15) << 2;
            int t = t0 + kj;
            const float* srcK = kg;
            const float* srcV = vg;
            int sz = 0;
            if (t < L) {
                const float* bp = memkv + (((size_t)t * BATCH + b) * NHEAD + h) * (2 * HCDIM);
                srcK = bp + dc;
                srcV = bp + HCDIM + dc;
                sz = 16;
            } else if (t < Teff) {
                int j = t - L;
                srcK = kg + ((size_t)j * BATCH + b) * CDIM + h * HCDIM + dc;
                srcV = vg + ((size_t)j * BATCH + b) * CDIM + h * HCDIM + dc;
                sz = 16;
            }
            cp16(kbase + (uint32_t)(kj * KSTR + dc) * 4u, srcK, sz);
            cp16(vbase + (uint32_t)(kj * VSTR + dc) * 4u, srcV, sz);
        }
        cp_commit();
    };

    if (ntile > 0) gather(0);

    for (int kt = 0; kt < ntile; kt++) {
        const int t0 = kt << 6;
        if (kt + 1 < ntile) { gather(kt + 1); cp_wait1(); }
        else                { cp_wait0(); }
        __syncthreads();

        const uint32_t* Kb = smu + (kt & 1) * KV_WORDS;
        const uint32_t* Vb = Kb + 64 * KSTR;

        // S = Q K^T
        float sv[8][4];
        #pragma unroll
        for (int ni = 0; ni < 8; ni++)
            #pragma unroll
            for (int r = 0; r < 4; r++) sv[ni][r] = 0.0f;

        #pragma unroll
        for (int ks = 0; ks < 8; ks++) {
            const int kk = ks << 3;
            #pragma unroll
            for (int ni = 0; ni < 8; ni++) {
                const uint32_t* bp = Kb + ((ni << 3) + g) * KSTR + kk + tig;
                mma_tf32(sv[ni], qf[ks][0], qf[ks][1], qf[ks][2], qf[ks][3],
                         bp[0], bp[4]);
            }
        }

        // Masking -- skipped entirely for tiles fully inside memory region
        if (t0 + 64 > L) {
            #pragma unroll
            for (int ni = 0; ni < 8; ni++) {
                #pragma unroll
                for (int cc = 0; cc < 2; cc++) {
                    int t = t0 + (ni << 3) + (tig << 1) + cc;
                    if (t >= Teff) {
                        sv[ni][cc] = -INFINITY;
                        sv[ni][2 + cc] = -INFINITY;
                    } else if (t >= L) {
                        int jn = t - L;
                        int r0 = s0 + qrow0;
                        if (mask[((size_t)r0 * QS + jn) * BATCH + b]) sv[ni][cc] = -INFINITY;
                        if (mask[((size_t)(r0 + 8) * QS + jn) * BATCH + b]) sv[ni][2 + cc] = -INFINITY;
                    }
                }
            }
        }

        // Online softmax per row-half (row spread over 4 tig lanes)
        #pragma unroll
        for (int half = 0; half < 2; half++) {
            const int o0i = half << 1;
            float rm = -INFINITY;
            #pragma unroll
            for (int ni = 0; ni < 8; ni++)
                rm = fmaxf(rm, fmaxf(sv[ni][o0i], sv[ni][o0i + 1]));
            rm = fmaxf(rm, __shfl_xor_sync(0xffffffffu, rm, 1));
            rm = fmaxf(rm, __shfl_xor_sync(0xffffffffu, rm, 2));
            float mn = fmaxf(mrow[half], rm);
            float factor = (mn == -INFINITY) ? 1.0f : __expf(mrow[half] - mn);
            float rs = 0.0f;
            #pragma unroll
            for (int ni = 0; ni < 8; ni++) {
                #pragma unroll
                for (int cc = 0; cc < 2; cc++) {
                    float p = (mn == -INFINITY) ? 0.0f : __expf(sv[ni][o0i + cc] - mn);
                    sv[ni][o0i + cc] = p;
                    rs += p;
                }
            }
            rs += __shfl_xor_sync(0xffffffffu, rs, 1);
            rs += __shfl_xor_sync(0xffffffffu, rs, 2);
            lrow[half] = lrow[half] * factor + rs;
            mrow[half] = mn;
            #pragma unroll
            for (int ni = 0; ni < 8; ni++) {
                oacc[ni][o0i] *= factor;
                oacc[ni][o0i + 1] *= factor;
            }
        }

        // O += P V. P C-frag -> A-frag via intra-group shuffles:
        // col c of block ks lives at lane (g*4 + (c>>1)), slot (c&1).
        const int srcA = (lane & ~3) + (tig >> 1);
        const int srcB = srcA + 2;
        const int sel  = tig & 1;
        #pragma unroll
        for (int ks = 0; ks < 8; ks++) {
            float s0a = __shfl_sync(0xffffffffu, sv[ks][0], srcA);
            float s1a = __shfl_sync(0xffffffffu, sv[ks][1], srcA);
            float s2a = __shfl_sync(0xffffffffu, sv[ks][2], srcA);
            float s3a = __shfl_sync(0xffffffffu, sv[ks][3], srcA);
            float s0b = __shfl_sync(0xffffffffu, sv[ks][0], srcB);
            float s1b = __shfl_sync(0xffffffffu, sv[ks][1], srcB);
            float s2b = __shfl_sync(0xffffffffu, sv[ks][2], srcB);
            float s3b = __shfl_sync(0xffffffffu, sv[ks][3], srcB);
            uint32_t pa0 = f2tf32(sel ? s1a : s0a);   // P[g][8ks+tig]
            uint32_t pa1 = f2tf32(sel ? s3a : s2a);   // P[g+8][8ks+tig]
            uint32_t pa2 = f2tf32(sel ? s1b : s0b);   // P[g][8ks+tig+4]
            uint32_t pa3 = f2tf32(sel ? s3b : s2b);   // P[g+8][8ks+tig+4]

            const int kk = ks << 3;
            #pragma unroll
            for (int ni = 0; ni < 8; ni++) {
                const uint32_t* bp = Vb + (kk + tig) * VSTR + (ni << 3) + g;
                mma_tf32(oacc[ni], pa0, pa1, pa2, pa3, bp[0], bp[4 * VSTR]);
            }
        }
        __syncthreads();  // done reading this stage before it becomes prefetch target
    }

    // Normalize and write x[s][b][c] (all-masked rows -> 0)
    #pragma unroll
    for (int half = 0; half < 2; half++) {
        float inv = (lrow[half] > 0.0f) ? 1.0f / lrow[half] : 0.0f;
        int row = s0 + qrow0 + (half << 3);
        float* orow = xout + ((size_t)row * BATCH + b) * CDIM + h * HCDIM;
        #pragma unroll
        for (int ni = 0; ni < 8; ni++) {
            int col = (ni << 3) + (tig << 1);
            float2 v = make_float2(oacc[ni][(half << 1)] * inv,
                                   oacc[ni][(half << 1) + 1] * inv);
            *(float2*)(orow + col) = v;
        }
    }
}

// ---------------------------------------------------------------------------
// Launch
// ---------------------------------------------------------------------------
extern "C" void kernel_launch(void* const* d_in, const int* in_sizes, int n_in,
                              void* d_out, int out_size)
{
    const float*         xq     = (const float*)d_in[0];
    const int*           pad    = (const int*)d_in[1];
    const unsigned char* mask   = (const unsigned char*)d_in[2];
    const int*           memlen = (const int*)d_in[3];
    const float*         memkv  = (const float*)d_in[4];
    const float* Wq = (const float*)d_in[5];  const float* bq = (const float*)d_in[6];
    const float* Wk = (const float*)d_in[7];  const float* bk = (const float*)d_in[8];
    const float* Wv = (const float*)d_in[9];  const float* bv = (const float*)d_in[10];
    const float* Wo = (const float*)d_in[11]; const float* bo = (const float*)d_in[12];
    float* out = (float*)d_out;

    float *gq, *gk, *gv, *gx;
    cudaGetSymbolAddress((void**)&gq, g_q);
    cudaGetSymbolAddress((void**)&gk, g_k);
    cudaGetSymbolAddress((void**)&gv, g_v);
    cudaGetSymbolAddress((void**)&gx, g_x);

    dim3 gg(CDIM / 128, NTOK / 128);  // (8, 32)
    // q/k/v projections: fp16 mma, rna-tf32-rounded stores
    gemm_f16_nt_bias<true><<<gg, 256>>>(xq, Wq, bq, gq);
    gemm_f16_nt_bias<true><<<gg, 256>>>(xq, Wk, bk, gk);
    gemm_f16_nt_bias<true><<<gg, 256>>>(xq, Wv, bv, gv);

    const int smem_bytes = 2 * KV_WORDS * (int)sizeof(uint32_t);  // 71680
    cudaFuncSetAttribute(attn_tc_kernel, cudaFuncAttributeMaxDynamicSharedMemorySize, smem_bytes);
    attn_tc_kernel<<<dim3(QS / 64, BATCH * NHEAD), 128, smem_bytes>>>(
        gq, gk, gv, memkv, memlen, pad, mask, gx);

    // Output projection: full fp32 store
    gemm_f16_nt_bias<false><<<gg, 256>>>(gx, Wo, bo, out);
}

// round 14
// speedup vs baseline: 1.5358x; 1.5358x over previous
#include <cuda_runtime.h>
#include <cuda_fp16.h>
#include <math.h>
#include <stdint.h>

// Problem constants
#define QS    512
#define BATCH 8
#define CDIM  1024
#define NHEAD 16
#define HCDIM 64
#define MMEM  1536
#define NTOK  (QS * BATCH)   // 4096

// Scratch (device globals: allocation-guard safe)
__device__ float g_q[NTOK * CDIM];
__device__ float g_k[NTOK * CDIM];
__device__ float g_v[NTOK * CDIM];
__device__ float g_x[NTOK * CDIM];

__device__ __forceinline__ uint32_t f2tf32(float f) {
    uint32_t u;
    asm("cvt.rna.tf32.f32 %0, %1;" : "=r"(u) : "f"(f));
    return u;
}

__device__ __forceinline__ void mma_tf32(float c[4],
    uint32_t a0, uint32_t a1, uint32_t a2, uint32_t a3,
    uint32_t b0, uint32_t b1)
{
    asm volatile(
        "mma.sync.aligned.m16n8k8.row.col.f32.tf32.tf32.f32 "
        "{%0,%1,%2,%3}, {%4,%5,%6,%7}, {%8,%9}, {%0,%1,%2,%3};"
        : "+f"(c[0]), "+f"(c[1]), "+f"(c[2]), "+f"(c[3])
        : "r"(a0), "r"(a1), "r"(a2), "r"(a3), "r"(b0), "r"(b1));
}

__device__ __forceinline__ void mma_f16(float c[4],
    uint32_t a0, uint32_t a1, uint32_t a2, uint32_t a3,
    uint32_t b0, uint32_t b1)
{
    asm volatile(
        "mma.sync.aligned.m16n8k16.row.col.f32.f16.f16.f32 "
        "{%0,%1,%2,%3}, {%4,%5,%6,%7}, {%8,%9}, {%0,%1,%2,%3};"
        : "+f"(c[0]), "+f"(c[1]), "+f"(c[2]), "+f"(c[3])
        : "r"(a0), "r"(a1), "r"(a2), "r"(a3), "r"(b0), "r"(b1));
}

__device__ __forceinline__ void cp16(uint32_t dst, const void* src, int sz) {
    asm volatile("cp.async.cg.shared.global [%0], [%1], 16, %2;"
                 :: "r"(dst), "l"(src), "r"(sz));
}
__device__ __forceinline__ void cp_commit() {
    asm volatile("cp.async.commit_group;");
}
__device__ __forceinline__ void cp_wait0() {
    asm volatile("cp.async.wait_group 0;");
}
__device__ __forceinline__ void cp_wait1() {
    asm volatile("cp.async.wait_group 1;");
}

// ---------------------------------------------------------------------------
// FP16 tensor-core GEMM: out[n][o] = sum_k A[n][k] * W[o][k] + bias[o]
// Block tile 128x128, k-chunk 32, 8 warps (2x4), warp tile 64x32.
// mma.sync.m16n8k16.f16 (f32 accum). Clock-normalized R12 evidence:
// ~53.5us/GEMM vs 64us for tf32 k8 -> keep fp16.
// Smem rows = 36 halves (72B): B-frag bank = (18g+tig)%32, all distinct.
// ROUND_OUT: store rna-tf32-rounded values (q/k/v path; exactly preserved
// by the attention kernel's truncating consumption). Out-proj: full fp32.
// ---------------------------------------------------------------------------
template <bool ROUND_OUT>
__global__ __launch_bounds__(256) void gemm_f16_nt_bias(
    const float* __restrict__ A, const float* __restrict__ W,
    const float* __restrict__ bias, float* __restrict__ out)
{
    __shared__ __half As[128 * 36];
    __shared__ __half Ws[128 * 36];

    const int tid  = threadIdx.x;
    const int lane = tid & 31;
    const int warp = tid >> 5;
    const int g    = lane >> 2;
    const int tig  = lane & 3;

    const int wm = (warp >> 2) * 64;
    const int wn = (warp & 3) * 32;

    const int n0 = blockIdx.y << 7;
    const int o0 = blockIdx.x << 7;

    const int lrow = tid >> 3;
    const int lcol = (tid & 7) << 2;   // half-index within 32-half chunk

    float c[4][4][4];
    #pragma unroll
    for (int mi = 0; mi < 4; mi++)
        #pragma unroll
        for (int ni = 0; ni < 4; ni++)
            #pragma unroll
            for (int r = 0; r < 4; r++) c[mi][ni][r] = 0.0f;

    float4 ra[4], rw[4];
    #pragma unroll
    for (int p = 0; p < 4; p++) {
        int r = lrow + (p << 5);
        ra[p] = *(const float4*)(A + (size_t)(n0 + r) * CDIM + lcol);
        rw[p] = *(const float4*)(W + (size_t)(o0 + r) * CDIM + lcol);
    }

    for (int k0 = 0; k0 < CDIM; k0 += 32) {
        #pragma unroll
        for (int p = 0; p < 4; p++) {
            int r = lrow + (p << 5);
            __half2 alo = __floats2half2_rn(ra[p].x, ra[p].y);
            __half2 ahi = __floats2half2_rn(ra[p].z, ra[p].w);
            *(__half2*)(As + r * 36 + lcol)     = alo;
            *(__half2*)(As + r * 36 + lcol + 2) = ahi;
            __half2 wlo = __floats2half2_rn(rw[p].x, rw[p].y);
            __half2 whi = __floats2half2_rn(rw[p].z, rw[p].w);
            *(__half2*)(Ws + r * 36 + lcol)     = wlo;
            *(__half2*)(Ws + r * 36 + lcol + 2) = whi;
        }
        __syncthreads();

        if (k0 + 32 < CDIM) {
            #pragma unroll
            for (int p = 0; p < 4; p++) {
                int r = lrow + (p << 5);
                ra[p] = *(const float4*)(A + (size_t)(n0 + r) * CDIM + k0 + 32 + lcol);
                rw[p] = *(const float4*)(W + (size_t)(o0 + r) * CDIM + k0 + 32 + lcol);
            }
        }

        #pragma unroll
        for (int ks = 0; ks < 2; ks++) {
            const int kk = ks << 4;   // 16 halves per mma
            uint32_t a[4][4], b[4][2];
            #pragma unroll
            for (int mi = 0; mi < 4; mi++) {
                const uint32_t* ap = (const uint32_t*)As
                    + (wm + (mi << 4) + g) * 18 + (kk >> 1) + tig;
                a[mi][0] = ap[0];            // (row g,    k 2tig..2tig+1)
                a[mi][1] = ap[8 * 18];       // (row g+8)
                a[mi][2] = ap[4];            // (row g,    k+8)
                a[mi][3] = ap[8 * 18 + 4];   // (row g+8,  k+8)
            }
            #pragma unroll
            for (int ni = 0; ni < 4; ni++) {
                const uint32_t* bp = (const uint32_t*)Ws
                    + (wn + (ni << 3) + g) * 18 + (kk >> 1) + tig;
                b[ni][0] = bp[0];
                b[ni][1] = bp[4];
            }
            #pragma unroll
            for (int mi = 0; mi < 4; mi++)
                #pragma unroll
                for (int ni = 0; ni < 4; ni++)
                    mma_f16(c[mi][ni], a[mi][0], a[mi][1], a[mi][2], a[mi][3],
                            b[ni][0], b[ni][1]);
        }
        __syncthreads();
    }

    #pragma unroll
    for (int mi = 0; mi < 4; mi++) {
        int row = n0 + wm + (mi << 4) + g;
        #pragma unroll
        for (int ni = 0; ni < 4; ni++) {
            int col = o0 + wn + (ni << 3) + (tig << 1);
            float b0 = bias[col], b1 = bias[col + 1];
            float r00 = c[mi][ni][0] + b0, r01 = c[mi][ni][1] + b1;
            float r10 = c[mi][ni][2] + b0, r11 = c[mi][ni][3] + b1;
            float2 v0, v1;
            if (ROUND_OUT) {
                v0 = make_float2(__uint_as_float(f2tf32(r00)), __uint_as_float(f2tf32(r01)));
                v1 = make_float2(__uint_as_float(f2tf32(r10)), __uint_as_float(f2tf32(r11)));
            } else {
                v0 = make_float2(r00, r01);
                v1 = make_float2(r10, r11);
            }
            *(float2*)(out + (size_t)row * CDIM + col) = v0;
            *(float2*)(out + (size_t)(row + 8) * CDIM + col) = v1;
        }
    }
}

// ---------------------------------------------------------------------------
// TF32 tensor-core flash attention, 2-stage cp.async pipelined KV gather.
// (VERBATIM round-11 winner: 171.6us measured on a normal-clock run.)
// ---------------------------------------------------------------------------
#define KSTR 68
#define VSTR 72
#define KV_WORDS (64 * KSTR + 64 * VSTR)   // one stage: 8960 words

__global__ __launch_bounds__(128) void attn_tc_kernel(
    const float* __restrict__ qg, const float* __restrict__ kg,
    const float* __restrict__ vg, const float* __restrict__ memkv,
    const int* __restrict__ memlen, const int* __restrict__ padv,
    const unsigned char* __restrict__ mask, float* __restrict__ xout)
{
    extern __shared__ uint32_t smu[];   // 2 * KV_WORDS = 17920 words = 71680 B
    const uint32_t smem_base = (uint32_t)__cvta_generic_to_shared(smu);

    const int tid  = threadIdx.x;
    const int lane = tid & 31;
    const int warp = tid >> 5;       // 0..3
    const int g    = lane >> 2;      // 0..7
    const int tig  = lane & 3;       // 0..3

    const int s0 = blockIdx.x << 6;
    const int b  = blockIdx.y >> 4;
    const int h  = blockIdx.y & 15;
    const int L  = memlen[b];
    const int P  = padv[b];
    const int Teff = L + P;
    const int qrow0 = warp * 16 + g;

    {
        float* Qst = (float*)smu;   // [qi][d] stride 68
        for (int i = tid; i < 1024; i += 128) {
            int qi = i >> 4;
            int dc = (i & 15) << 2;
            float4 qv = *(const float4*)(qg + ((size_t)(s0 + qi) * BATCH + b) * CDIM + h * HCDIM + dc);
            *(float4*)(Qst + qi * KSTR + dc) = qv;
        }
    }
    __syncthreads();

    uint32_t qf[8][4];
    {
        const float* q0 = (const float*)smu + qrow0 * KSTR;
        const float* q8 = q0 + 8 * KSTR;
        #pragma unroll
        for (int ks = 0; ks < 8; ks++) {
            const int kk = ks << 3;
            qf[ks][0] = f2tf32(q0[kk + tig] * 0.125f);
            qf[ks][1] = f2tf32(q8[kk + tig] * 0.125f);
            qf[ks][2] = f2tf32(q0[kk + tig + 4] * 0.125f);
            qf[ks][3] = f2tf32(q8[kk + tig + 4] * 0.125f);
        }
    }
    __syncthreads();

    float oacc[8][4];
    #pragma unroll
    for (int ni = 0; ni < 8; ni++)
        #pragma unroll
        for (int r = 0; r < 4; r++) oacc[ni][r] = 0.0f;
    float mrow[2] = { -INFINITY, -INFINITY };
    float lrow[2] = { 0.0f, 0.0f };

    const int ntile = (Teff + 63) >> 6;

    auto gather = [&](int kt) {
        const int t0 = kt << 6;
        const uint32_t kbase = smem_base + (uint32_t)((kt & 1) * KV_WORDS) * 4u;
        const uint32_t vbase = kbase + 64 * KSTR * 4u;
        for (int i = tid; i < 1024; i += 128) {
            int kj = i >> 4;
            int dc = (i & 15) << 2;
            int t = t0 + kj;
            const float* srcK = kg;
            const float* srcV = vg;
            int sz = 0;
            if (t < L) {
                const float* bp = memkv + (((size_t)t * BATCH + b) * NHEAD + h) * (2 * HCDIM);
                srcK = bp + dc;
                srcV = bp + HCDIM + dc;
                sz = 16;
            } else if (t < Teff) {
                int j = t - L;
                srcK = kg + ((size_t)j * BATCH + b) * CDIM + h * HCDIM + dc;
                srcV = vg + ((size_t)j * BATCH + b) * CDIM + h * HCDIM + dc;
                sz = 16;
            }
            cp16(kbase + (uint32_t)(kj * KSTR + dc) * 4u, srcK, sz);
            cp16(vbase + (uint32_t)(kj * VSTR + dc) * 4u, srcV, sz);
        }
        cp_commit();
    };

    if (ntile > 0) gather(0);

    for (int kt = 0; kt < ntile; kt++) {
        const int t0 = kt << 6;
        if (kt + 1 < ntile) { gather(kt + 1); cp_wait1(); }
        else                { cp_wait0(); }
        __syncthreads();

        const uint32_t* Kb = smu + (kt & 1) * KV_WORDS;
        const uint32_t* Vb = Kb + 64 * KSTR;

        float sv[8][4];
        #pragma unroll
        for (int ni = 0; ni < 8; ni++)
            #pragma unroll
            for (int r = 0; r < 4; r++) sv[ni][r] = 0.0f;

        #pragma unroll
        for (int ks = 0; ks < 8; ks++) {
            const int kk = ks << 3;
            #pragma unroll
            for (int ni = 0; ni < 8; ni++) {
                const uint32_t* bp = Kb + ((ni << 3) + g) * KSTR + kk + tig;
                mma_tf32(sv[ni], qf[ks][0], qf[ks][1], qf[ks][2], qf[ks][3],
                         bp[0], bp[4]);
            }
        }

        if (t0 + 64 > L) {
            #pragma unroll
            for (int ni = 0; ni < 8; ni++) {
                #pragma unroll
                for (int cc = 0; cc < 2; cc++) {
                    int t = t0 + (ni << 3) + (tig << 1) + cc;
                    if (t >= Teff) {
                        sv[ni][cc] = -INFINITY;
                        sv[ni][2 + cc] = -INFINITY;
                    } else if (t >= L) {
                        int jn = t - L;
                        int r0 = s0 + qrow0;
                        if (mask[((size_t)r0 * QS + jn) * BATCH + b]) sv[ni][cc] = -INFINITY;
                        if (mask[((size_t)(r0 + 8) * QS + jn) * BATCH + b]) sv[ni][2 + cc] = -INFINITY;
                    }
                }
            }
        }

        #pragma unroll
        for (int half = 0; half < 2; half++) {
            const int o0i = half << 1;
            float rm = -INFINITY;
            #pragma unroll
            for (int ni = 0; ni < 8; ni++)
                rm = fmaxf(rm, fmaxf(sv[ni][o0i], sv[ni][o0i + 1]));
            rm = fmaxf(rm, __shfl_xor_sync(0xffffffffu, rm, 1));
            rm = fmaxf(rm, __shfl_xor_sync(0xffffffffu, rm, 2));
            float mn = fmaxf(mrow[half], rm);
            float factor = (mn == -INFINITY) ? 1.0f : __expf(mrow[half] - mn);
            float rs = 0.0f;
            #pragma unroll
            for (int ni = 0; ni < 8; ni++) {
                #pragma unroll
                for (int cc = 0; cc < 2; cc++) {
                    float p = (mn == -INFINITY) ? 0.0f : __expf(sv[ni][o0i + cc] - mn);
                    sv[ni][o0i + cc] = p;
                    rs += p;
                }
            }
            rs += __shfl_xor_sync(0xffffffffu, rs, 1);
            rs += __shfl_xor_sync(0xffffffffu, rs, 2);
            lrow[half] = lrow[half] * factor + rs;
            mrow[half] = mn;
            #pragma unroll
            for (int ni = 0; ni < 8; ni++) {
                oacc[ni][o0i] *= factor;
                oacc[ni][o0i + 1] *= factor;
            }
        }

        const int srcA = (lane & ~3) + (tig >> 1);
        const int srcB = srcA + 2;
        const int sel  = tig & 1;
        #pragma unroll
        for (int ks = 0; ks < 8; ks++) {
            float s0a = __shfl_sync(0xffffffffu, sv[ks][0], srcA);
            float s1a = __shfl_sync(0xffffffffu, sv[ks][1], srcA);
            float s2a = __shfl_sync(0xffffffffu, sv[ks][2], srcA);
            float s3a = __shfl_sync(0xffffffffu, sv[ks][3], srcA);
            float s0b = __shfl_sync(0xffffffffu, sv[ks][0], srcB);
            float s1b = __shfl_sync(0xffffffffu, sv[ks][1], srcB);
            float s2b = __shfl_sync(0xffffffffu, sv[ks][2], srcB);
            float s3b = __shfl_sync(0xffffffffu, sv[ks][3], srcB);
            uint32_t pa0 = f2tf32(sel ? s1a : s0a);   // P[g][8ks+tig]
            uint32_t pa1 = f2tf32(sel ? s3a : s2a);   // P[g+8][8ks+tig]
            uint32_t pa2 = f2tf32(sel ? s1b : s0b);   // P[g][8ks+tig+4]
            uint32_t pa3 = f2tf32(sel ? s3b : s2b);   // P[g+8][8ks+tig+4]

            const int kk = ks << 3;
            #pragma unroll
            for (int ni = 0; ni < 8; ni++) {
                const uint32_t* bp = Vb + (kk + tig) * VSTR + (ni << 3) + g;
                mma_tf32(oacc[ni], pa0, pa1, pa2, pa3, bp[0], bp[4 * VSTR]);
            }
        }
        __syncthreads();
    }

    #pragma unroll
    for (int half = 0; half < 2; half++) {
        float inv = (lrow[half] > 0.0f) ? 1.0f / lrow[half] : 0.0f;
        int row = s0 + qrow0 + (half << 3);
        float* orow = xout + ((size_t)row * BATCH + b) * CDIM + h * HCDIM;
        #pragma unroll
        for (int ni = 0; ni < 8; ni++) {
            int col = (ni << 3) + (tig << 1);
            float2 v = make_float2(oacc[ni][(half << 1)] * inv,
                                   oacc[ni][(half << 1) + 1] * inv);
            *(float2*)(orow + col) = v;
        }
    }
}

// ---------------------------------------------------------------------------
// Launch
// ---------------------------------------------------------------------------
extern "C" void kernel_launch(void* const* d_in, const int* in_sizes, int n_in,
                              void* d_out, int out_size)
{
    const float*         xq     = (const float*)d_in[0];
    const int*           pad    = (const int*)d_in[1];
    const unsigned char* mask   = (const unsigned char*)d_in[2];
    const int*           memlen = (const int*)d_in[3];
    const float*         memkv  = (const float*)d_in[4];
    const float* Wq = (const float*)d_in[5];  const float* bq = (const float*)d_in[6];
    const float* Wk = (const float*)d_in[7];  const float* bk = (const float*)d_in[8];
    const float* Wv = (const float*)d_in[9];  const float* bv = (const float*)d_in[10];
    const float* Wo = (const float*)d_in[11]; const float* bo = (const float*)d_in[12];
    float* out = (float*)d_out;

    float *gq, *gk, *gv, *gx;
    cudaGetSymbolAddress((void**)&gq, g_q);
    cudaGetSymbolAddress((void**)&gk, g_k);
    cudaGetSymbolAddress((void**)&gv, g_v);
    cudaGetSymbolAddress((void**)&gx, g_x);

    dim3 gg(CDIM / 128, NTOK / 128);  // (8, 32)
    // q/k/v projections: fp16 mma, rna-tf32-rounded stores
    gemm_f16_nt_bias<true><<<gg, 256>>>(xq, Wq, bq, gq);
    gemm_f16_nt_bias<true><<<gg, 256>>>(xq, Wk, bk, gk);
    gemm_f16_nt_bias<true><<<gg, 256>>>(xq, Wv, bv, gv);

    const int smem_bytes = 2 * KV_WORDS * (int)sizeof(uint32_t);  // 71680
    cudaFuncSetAttribute(attn_tc_kernel, cudaFuncAttributeMaxDynamicSharedMemorySize, smem_bytes);
    attn_tc_kernel<<<dim3(QS / 64, BATCH * NHEAD), 128, smem_bytes>>>(
        gq, gk, gv, memkv, memlen, pad, mask, gx);

    // Output projection: full fp32 store
    gemm_f16_nt_bias<false><<<gg, 256>>>(gx, Wo, bo, out);
}

// round 15
// speedup vs baseline: 1.6735x; 1.0897x over previous
#include <cuda_runtime.h>
#include <cuda_fp16.h>
#include <math.h>
#include <stdint.h>

// Problem constants
#define QS    512
#define BATCH 8
#define CDIM  1024
#define NHEAD 16
#define HCDIM 64
#define MMEM  1536
#define NTOK  (QS * BATCH)   // 4096
#define MKV_ELEMS (MMEM * BATCH * NHEAD * 2 * HCDIM)   // 25165824

// Scratch (device globals: allocation-guard safe)
__device__ float  g_q[NTOK * CDIM];
__device__ __half g_kh[NTOK * CDIM];
__device__ __half g_vh[NTOK * CDIM];
__device__ float  g_x[NTOK * CDIM];
__device__ __half g_mkv[MKV_ELEMS];   // fp16 copy of memory_kv (rna)

__device__ __forceinline__ uint32_t f2tf32(float f) {
    uint32_t u;
    asm("cvt.rna.tf32.f32 %0, %1;" : "=r"(u) : "f"(f));
    return u;
}

__device__ __forceinline__ void mma_f16(float c[4],
    uint32_t a0, uint32_t a1, uint32_t a2, uint32_t a3,
    uint32_t b0, uint32_t b1)
{
    asm volatile(
        "mma.sync.aligned.m16n8k16.row.col.f32.f16.f16.f32 "
        "{%0,%1,%2,%3}, {%4,%5,%6,%7}, {%8,%9}, {%0,%1,%2,%3};"
        : "+f"(c[0]), "+f"(c[1]), "+f"(c[2]), "+f"(c[3])
        : "r"(a0), "r"(a1), "r"(a2), "r"(a3), "r"(b0), "r"(b1));
}

__device__ __forceinline__ void ldsm_x4(uint32_t& r0, uint32_t& r1,
                                        uint32_t& r2, uint32_t& r3, uint32_t addr)
{
    asm volatile("ldmatrix.sync.aligned.m8n8.x4.shared.b16 {%0,%1,%2,%3}, [%4];"
                 : "=r"(r0), "=r"(r1), "=r"(r2), "=r"(r3) : "r"(addr));
}
__device__ __forceinline__ void ldsm_x4_t(uint32_t& r0, uint32_t& r1,
                                          uint32_t& r2, uint32_t& r3, uint32_t addr)
{
    asm volatile("ldmatrix.sync.aligned.m8n8.x4.trans.shared.b16 {%0,%1,%2,%3}, [%4];"
                 : "=r"(r0), "=r"(r1), "=r"(r2), "=r"(r3) : "r"(addr));
}

__device__ __forceinline__ void cp16(uint32_t dst, const void* src, int sz) {
    asm volatile("cp.async.cg.shared.global [%0], [%1], 16, %2;"
                 :: "r"(dst), "l"(src), "r"(sz));
}
__device__ __forceinline__ void cp_commit() {
    asm volatile("cp.async.commit_group;");
}
__device__ __forceinline__ void cp_wait0() {
    asm volatile("cp.async.wait_group 0;");
}
__device__ __forceinline__ void cp_wait1() {
    asm volatile("cp.async.wait_group 1;");
}

// ---------------------------------------------------------------------------
// Pre-pass: memory_kv fp32 -> fp16 (rna). 8 halves per thread-chunk.
// ---------------------------------------------------------------------------
__global__ __launch_bounds__(256) void mkv_to_f16(
    const float* __restrict__ src, __half* __restrict__ dst)
{
    int idx = blockIdx.x * 256 + threadIdx.x;    // chunk of 8 elems
    size_t base = (size_t)idx * 8;
    float4 a = *(const float4*)(src + base);
    float4 b = *(const float4*)(src + base + 4);
    __half2 h0 = __floats2half2_rn(a.x, a.y);
    __half2 h1 = __floats2half2_rn(a.z, a.w);
    __half2 h2 = __floats2half2_rn(b.x, b.y);
    __half2 h3 = __floats2half2_rn(b.z, b.w);
    *(uint4*)(dst + base) = make_uint4(
        *(uint32_t*)&h0, *(uint32_t*)&h1, *(uint32_t*)&h2, *(uint32_t*)&h3);
}

// ---------------------------------------------------------------------------
// FP16 tensor-core GEMM (R14 winner core): out = A @ W.T + bias
// OM=0: fp32 store (out proj). OM=1: fp32 tf32-rna store (q).
// OM=2: fp16 rna store (k, v -> feeds fp16 attention gather directly).
// ---------------------------------------------------------------------------
template <int OM>
__global__ __launch_bounds__(256) void gemm_f16_nt_bias(
    const float* __restrict__ A, const float* __restrict__ W,
    const float* __restrict__ bias, void* __restrict__ outp)
{
    __shared__ __half As[128 * 36];
    __shared__ __half Ws[128 * 36];

    const int tid  = threadIdx.x;
    const int lane = tid & 31;
    const int warp = tid >> 5;
    const int g    = lane >> 2;
    const int tig  = lane & 3;

    const int wm = (warp >> 2) * 64;
    const int wn = (warp & 3) * 32;

    const int n0 = blockIdx.y << 7;
    const int o0 = blockIdx.x << 7;

    const int lrow = tid >> 3;
    const int lcol = (tid & 7) << 2;

    float c[4][4][4];
    #pragma unroll
    for (int mi = 0; mi < 4; mi++)
        #pragma unroll
        for (int ni = 0; ni < 4; ni++)
            #pragma unroll
            for (int r = 0; r < 4; r++) c[mi][ni][r] = 0.0f;

    float4 ra[4], rw[4];
    #pragma unroll
    for (int p = 0; p < 4; p++) {
        int r = lrow + (p << 5);
        ra[p] = *(const float4*)(A + (size_t)(n0 + r) * CDIM + lcol);
        rw[p] = *(const float4*)(W + (size_t)(o0 + r) * CDIM + lcol);
    }

    for (int k0 = 0; k0 < CDIM; k0 += 32) {
        #pragma unroll
        for (int p = 0; p < 4; p++) {
            int r = lrow + (p << 5);
            __half2 alo = __floats2half2_rn(ra[p].x, ra[p].y);
            __half2 ahi = __floats2half2_rn(ra[p].z, ra[p].w);
            *(__half2*)(As + r * 36 + lcol)     = alo;
            *(__half2*)(As + r * 36 + lcol + 2) = ahi;
            __half2 wlo = __floats2half2_rn(rw[p].x, rw[p].y);
            __half2 whi = __floats2half2_rn(rw[p].z, rw[p].w);
            *(__half2*)(Ws + r * 36 + lcol)     = wlo;
            *(__half2*)(Ws + r * 36 + lcol + 2) = whi;
        }
        __syncthreads();

        if (k0 + 32 < CDIM) {
            #pragma unroll
            for (int p = 0; p < 4; p++) {
                int r = lrow + (p << 5);
                ra[p] = *(const float4*)(A + (size_t)(n0 + r) * CDIM + k0 + 32 + lcol);
                rw[p] = *(const float4*)(W + (size_t)(o0 + r) * CDIM + k0 + 32 + lcol);
            }
        }

        #pragma unroll
        for (int ks = 0; ks < 2; ks++) {
            const int kk = ks << 4;
            uint32_t a[4][4], b[4][2];
            #pragma unroll
            for (int mi = 0; mi < 4; mi++) {
                const uint32_t* ap = (const uint32_t*)As
                    + (wm + (mi << 4) + g) * 18 + (kk >> 1) + tig;
                a[mi][0] = ap[0];
                a[mi][1] = ap[8 * 18];
                a[mi][2] = ap[4];
                a[mi][3] = ap[8 * 18 + 4];
            }
            #pragma unroll
            for (int ni = 0; ni < 4; ni++) {
                const uint32_t* bp = (const uint32_t*)Ws
                    + (wn + (ni << 3) + g) * 18 + (kk >> 1) + tig;
                b[ni][0] = bp[0];
                b[ni][1] = bp[4];
            }
            #pragma unroll
            for (int mi = 0; mi < 4; mi++)
                #pragma unroll
                for (int ni = 0; ni < 4; ni++)
                    mma_f16(c[mi][ni], a[mi][0], a[mi][1], a[mi][2], a[mi][3],
                            b[ni][0], b[ni][1]);
        }
        __syncthreads();
    }

    #pragma unroll
    for (int mi = 0; mi < 4; mi++) {
        int row = n0 + wm + (mi << 4) + g;
        #pragma unroll
        for (int ni = 0; ni < 4; ni++) {
            int col = o0 + wn + (ni << 3) + (tig << 1);
            float b0 = bias[col], b1 = bias[col + 1];
            float r00 = c[mi][ni][0] + b0, r01 = c[mi][ni][1] + b1;
            float r10 = c[mi][ni][2] + b0, r11 = c[mi][ni][3] + b1;
            if (OM == 2) {
                __half* out = (__half*)outp;
                __half2 h0 = __floats2half2_rn(r00, r01);
                __half2 h1 = __floats2half2_rn(r10, r11);
                *(__half2*)(out + (size_t)row * CDIM + col) = h0;
                *(__half2*)(out + (size_t)(row + 8) * CDIM + col) = h1;
            } else {
                float* out = (float*)outp;
                float2 v0, v1;
                if (OM == 1) {
                    v0 = make_float2(__uint_as_float(f2tf32(r00)), __uint_as_float(f2tf32(r01)));
                    v1 = make_float2(__uint_as_float(f2tf32(r10)), __uint_as_float(f2tf32(r11)));
                } else {
                    v0 = make_float2(r00, r01);
                    v1 = make_float2(r10, r11);
                }
                *(float2*)(out + (size_t)row * CDIM + col) = v0;
                *(float2*)(out + (size_t)(row + 8) * CDIM + col) = v1;
            }
        }
    }
}

// ---------------------------------------------------------------------------
// FP16 tensor-core flash attention, 2-stage cp.async pipelined fp16 KV gather.
// Grid: (QS/64, BATCH*NHEAD). Block: 128 threads (4 warps), 64q x 64k tiles.
// K smem [key][d] halves (stride 72), V smem [t][c] halves (stride 72).
// QK B-frags: ldmatrix.x4 (non-trans); PV B-frags: ldmatrix.x4.trans.
// P A-frags come straight from S C-frags (same column pairing) -> no shuffles.
// ---------------------------------------------------------------------------
#define KSTR_H   72                      // halves per K/V smem row (144 B)
#define TILE_B   (64 * KSTR_H * 2)       // 9216 B per K or V tile
#define STAGE_B  (2 * TILE_B)            // 18432 B per stage
#define ATTN_SMEM (2 * STAGE_B)          // 36864 B

__global__ __launch_bounds__(128) void attn_f16_kernel(
    const float* __restrict__ qg, const __half* __restrict__ kh,
    const __half* __restrict__ vh, const __half* __restrict__ mkv,
    const int* __restrict__ memlen, const int* __restrict__ padv,
    const unsigned char* __restrict__ mask, float* __restrict__ xout)
{
    extern __shared__ char smc[];
    const uint32_t smem_base = (uint32_t)__cvta_generic_to_shared(smc);

    const int tid  = threadIdx.x;
    const int lane = tid & 31;
    const int warp = tid >> 5;       // 0..3
    const int g    = lane >> 2;      // 0..7
    const int tig  = lane & 3;       // 0..3

    const int s0 = blockIdx.x << 6;
    const int b  = blockIdx.y >> 4;
    const int h  = blockIdx.y & 15;
    const int L  = memlen[b];
    const int P  = padv[b];
    const int Teff = L + P;
    const int qrow0 = warp * 16 + g;

    // ---- Stage Q (fp32) through stage-buffer 0, build fp16 A-fragments ----
    {
        float* Qst = (float*)smc;    // [qi][d] stride 68 floats (17408 B fits)
        for (int i = tid; i < 1024; i += 128) {
            int qi = i >> 4;
            int dc = (i & 15) << 2;
            float4 qv = *(const float4*)(qg + ((size_t)(s0 + qi) * BATCH + b) * CDIM + h * HCDIM + dc);
            *(float4*)(Qst + qi * 68 + dc) = qv;
        }
    }
    __syncthreads();

    uint32_t qf[4][4];   // [k-chunk of 16][a0..a3]
    {
        const float* q0 = (const float*)smc + qrow0 * 68;
        const float* q8 = q0 + 8 * 68;
        #pragma unroll
        for (int ks = 0; ks < 4; ks++) {
            const int kk = ks << 4;
            __half2 t0h = __floats2half2_rn(q0[kk + 2*tig] * 0.125f,     q0[kk + 2*tig + 1] * 0.125f);
            __half2 t1h = __floats2half2_rn(q8[kk + 2*tig] * 0.125f,     q8[kk + 2*tig + 1] * 0.125f);
            __half2 t2h = __floats2half2_rn(q0[kk + 2*tig + 8] * 0.125f, q0[kk + 2*tig + 9] * 0.125f);
            __half2 t3h = __floats2half2_rn(q8[kk + 2*tig + 8] * 0.125f, q8[kk + 2*tig + 9] * 0.125f);
            qf[ks][0] = *(uint32_t*)&t0h;
            qf[ks][1] = *(uint32_t*)&t1h;
            qf[ks][2] = *(uint32_t*)&t2h;
            qf[ks][3] = *(uint32_t*)&t3h;
        }
    }
    __syncthreads();   // Q staging consumed before gather overwrites buffer 0

    float oacc[8][4];
    #pragma unroll
    for (int ni = 0; ni < 8; ni++)
        #pragma unroll
        for (int r = 0; r < 4; r++) oacc[ni][r] = 0.0f;
    float mrow[2] = { -INFINITY, -INFINITY };
    float lrow[2] = { 0.0f, 0.0f };

    const int ntile = (Teff + 63) >> 6;

    // ---- fp16 KV gather: 8 halves (16 B) per cp.async chunk ----
    auto gather = [&](int kt) {
        const int t0 = kt << 6;
        const uint32_t kbase = smem_base + (uint32_t)((kt & 1) * STAGE_B);
        const uint32_t vbase = kbase + TILE_B;
        for (int i = tid; i < 512; i += 128) {
            int kj = i >> 3;          // key row 0..63
            int c8 = i & 7;           // chunk of 8 halves within 64
            int t = t0 + kj;
            const __half* srcK = kh;
            const __half* srcV = vh;
            int sz = 0;
            if (t < L) {
                const __half* bp = mkv + (((size_t)t * BATCH + b) * NHEAD + h) * (2 * HCDIM);
                srcK = bp + c8 * 8;
                srcV = bp + HCDIM + c8 * 8;
                sz = 16;
            } else if (t < Teff) {
                int j = t - L;
                size_t ro = ((size_t)j * BATCH + b) * CDIM + h * HCDIM + c8 * 8;
                srcK = kh + ro;
                srcV = vh + ro;
                sz = 16;
            }
            uint32_t doff = (uint32_t)(kj * (KSTR_H * 2) + c8 * 16);
            cp16(kbase + doff, srcK, sz);
            cp16(vbase + doff, srcV, sz);
        }
        cp_commit();
    };

    if (ntile > 0) gather(0);

    for (int kt = 0; kt < ntile; kt++) {
        const int t0 = kt << 6;
        if (kt + 1 < ntile) { gather(kt + 1); cp_wait1(); }
        else                { cp_wait0(); }
        __syncthreads();

        const uint32_t kb = smem_base + (uint32_t)((kt & 1) * STAGE_B);
        const uint32_t vb = kb + TILE_B;

        // ---- S = Q K^T (fp16 mma, 32 mma) ----
        float sv[8][4];
        #pragma unroll
        for (int ni = 0; ni < 8; ni++)
            #pragma unroll
            for (int r = 0; r < 4; r++) sv[ni][r] = 0.0f;

        #pragma unroll
        for (int ks = 0; ks < 4; ks++) {
            #pragma unroll
            for (int j = 0; j < 4; j++) {
                // tiles: (ni=2j,b0),(2j,b1),(2j+1,b0),(2j+1,b1)
                int q4 = lane >> 3;                 // 0..3
                int ni = 2 * j + (q4 >> 1);
                int khalf = q4 & 1;
                uint32_t addr = kb + (uint32_t)(((ni << 3) + (lane & 7)) * (KSTR_H * 2)
                                                + (ks << 5) + (khalf << 4));
                uint32_t b00, b01, b10, b11;
                ldsm_x4(b00, b01, b10, b11, addr);
                mma_f16(sv[2 * j],     qf[ks][0], qf[ks][1], qf[ks][2], qf[ks][3], b00, b01);
                mma_f16(sv[2 * j + 1], qf[ks][0], qf[ks][1], qf[ks][2], qf[ks][3], b10, b11);
            }
        }

        // ---- Masking (skipped for tiles fully inside memory) ----
        if (t0 + 64 > L) {
            #pragma unroll
            for (int ni = 0; ni < 8; ni++) {
                #pragma unroll
                for (int cc = 0; cc < 2; cc++) {
                    int t = t0 + (ni << 3) + (tig << 1) + cc;
                    if (t >= Teff) {
                        sv[ni][cc] = -INFINITY;
                        sv[ni][2 + cc] = -INFINITY;
                    } else if (t >= L) {
                        int jn = t - L;
                        int r0 = s0 + qrow0;
                        if (mask[((size_t)r0 * QS + jn) * BATCH + b]) sv[ni][cc] = -INFINITY;
                        if (mask[((size_t)(r0 + 8) * QS + jn) * BATCH + b]) sv[ni][2 + cc] = -INFINITY;
                    }
                }
            }
        }

        // ---- Online softmax per row-half ----
        #pragma unroll
        for (int half = 0; half < 2; half++) {
            const int o0i = half << 1;
            float rm = -INFINITY;
            #pragma unroll
            for (int ni = 0; ni < 8; ni++)
                rm = fmaxf(rm, fmaxf(sv[ni][o0i], sv[ni][o0i + 1]));
            rm = fmaxf(rm, __shfl_xor_sync(0xffffffffu, rm, 1));
            rm = fmaxf(rm, __shfl_xor_sync(0xffffffffu, rm, 2));
            float mn = fmaxf(mrow[half], rm);
            float factor = (mn == -INFINITY) ? 1.0f : __expf(mrow[half] - mn);
            float rs = 0.0f;
            #pragma unroll
            for (int ni = 0; ni < 8; ni++) {
                #pragma unroll
                for (int cc = 0; cc < 2; cc++) {
                    float p = (mn == -INFINITY) ? 0.0f : __expf(sv[ni][o0i + cc] - mn);
                    sv[ni][o0i + cc] = p;
                    rs += p;
                }
            }
            rs += __shfl_xor_sync(0xffffffffu, rs, 1);
            rs += __shfl_xor_sync(0xffffffffu, rs, 2);
            lrow[half] = lrow[half] * factor + rs;
            mrow[half] = mn;
            #pragma unroll
            for (int ni = 0; ni < 8; ni++) {
                oacc[ni][o0i] *= factor;
                oacc[ni][o0i + 1] *= factor;
            }
        }

        // ---- P A-frags: direct pack from C-frags (no shuffles) ----
        uint32_t pa[4][4];
        #pragma unroll
        for (int ks = 0; ks < 4; ks++) {
            __half2 p0 = __floats2half2_rn(sv[2*ks][0],     sv[2*ks][1]);
            __half2 p1 = __floats2half2_rn(sv[2*ks][2],     sv[2*ks][3]);
            __half2 p2 = __floats2half2_rn(sv[2*ks + 1][0], sv[2*ks + 1][1]);
            __half2 p3 = __floats2half2_rn(sv[2*ks + 1][2], sv[2*ks + 1][3]);
            pa[ks][0] = *(uint32_t*)&p0;
            pa[ks][1] = *(uint32_t*)&p1;
            pa[ks][2] = *(uint32_t*)&p2;
            pa[ks][3] = *(uint32_t*)&p3;
        }

        // ---- O += P V (fp16 mma, V B-frags via ldmatrix.trans) ----
        #pragma unroll
        for (int ni = 0; ni < 8; ni++) {
            #pragma unroll
            for (int p = 0; p < 2; p++) {
                // tiles: (ks=2p, t-low8), (2p, t-high8), (2p+1, low), (2p+1, high)
                int q4 = lane >> 3;
                int ksl = 2 * p + (q4 >> 1);
                int tb  = q4 & 1;
                int t   = (ksl << 4) + (tb << 3) + (lane & 7);
                uint32_t addr = vb + (uint32_t)(t * (KSTR_H * 2) + (ni << 4));
                uint32_t v00, v01, v10, v11;
                ldsm_x4_t(v00, v01, v10, v11, addr);
                mma_f16(oacc[ni], pa[2*p][0],   pa[2*p][1],   pa[2*p][2],   pa[2*p][3],   v00, v01);
                mma_f16(oacc[ni], pa[2*p+1][0], pa[2*p+1][1], pa[2*p+1][2], pa[2*p+1][3], v10, v11);
            }
        }
        __syncthreads();   // done reading this stage before it becomes prefetch target
    }

    // ---- Normalize and write x[s][b][c] (all-masked rows -> 0) ----
    #pragma unroll
    for (int half = 0; half < 2; half++) {
        float inv = (lrow[half] > 0.0f) ? 1.0f / lrow[half] : 0.0f;
        int row = s0 + qrow0 + (half << 3);
        float* orow = xout + ((size_t)row * BATCH + b) * CDIM + h * HCDIM;
        #pragma unroll
        for (int ni = 0; ni < 8; ni++) {
            int col = (ni << 3) + (tig << 1);
            float2 v = make_float2(oacc[ni][(half << 1)] * inv,
                                   oacc[ni][(half << 1) + 1] * inv);
            *(float2*)(orow + col) = v;
        }
    }
}

// ---------------------------------------------------------------------------
// Launch
// ---------------------------------------------------------------------------
extern "C" void kernel_launch(void* const* d_in, const int* in_sizes, int n_in,
                              void* d_out, int out_size)
{
    const float*         xq     = (const float*)d_in[0];
    const int*           pad    = (const int*)d_in[1];
    const unsigned char* mask   = (const unsigned char*)d_in[2];
    const int*           memlen = (const int*)d_in[3];
    const float*         memkv  = (const float*)d_in[4];
    const float* Wq = (const float*)d_in[5];  const float* bq = (const float*)d_in[6];
    const float* Wk = (const float*)d_in[7];  const float* bk = (const float*)d_in[8];
    const float* Wv = (const float*)d_in[9];  const float* bv = (const float*)d_in[10];
    const float* Wo = (const float*)d_in[11]; const float* bo = (const float*)d_in[12];
    float* out = (float*)d_out;

    float *gq, *gx;
    __half *gkh, *gvh, *gmkv;
    cudaGetSymbolAddress((void**)&gq,  g_q);
    cudaGetSymbolAddress((void**)&gkh, g_kh);
    cudaGetSymbolAddress((void**)&gvh, g_vh);
    cudaGetSymbolAddress((void**)&gx,  g_x);
    cudaGetSymbolAddress((void**)&gmkv, g_mkv);

    // memkv fp32 -> fp16 (rna) pre-pass
    mkv_to_f16<<<MKV_ELEMS / (256 * 8), 256>>>(memkv, gmkv);

    dim3 gg(CDIM / 128, NTOK / 128);  // (8, 32)
    gemm_f16_nt_bias<1><<<gg, 256>>>(xq, Wq, bq, gq);    // q: fp32 tf32-rounded
    gemm_f16_nt_bias<2><<<gg, 256>>>(xq, Wk, bk, gkh);   // k: fp16
    gemm_f16_nt_bias<2><<<gg, 256>>>(xq, Wv, bv, gvh);   // v: fp16

    cudaFuncSetAttribute(attn_f16_kernel, cudaFuncAttributeMaxDynamicSharedMemorySize, ATTN_SMEM);
    attn_f16_kernel<<<dim3(QS / 64, BATCH * NHEAD), 128, ATTN_SMEM>>>(
        gq, gkh, gvh, gmkv, memlen, pad, mask, gx);

    gemm_f16_nt_bias<0><<<gg, 256>>>(gx, Wo, bo, out);   // out proj: fp32
}

// round 17
// speedup vs baseline: 2.1878x; 1.3073x over previous
#include <cuda_runtime.h>
#include <cuda_fp16.h>
#include <math.h>
#include <stdint.h>

// Problem constants
#define QS    512
#define BATCH 8
#define CDIM  1024
#define NHEAD 16
#define HCDIM 64
#define MMEM  1536
#define NTOK  (QS * BATCH)   // 4096
#define MKV_ELEMS (MMEM * BATCH * NHEAD * 2 * HCDIM)   // 25165824

// Scratch (device globals: allocation-guard safe)
__device__ __half g_xqh[NTOK * CDIM];     // xq fp16
__device__ __half g_wq[CDIM * CDIM], g_wk[CDIM * CDIM];
__device__ __half g_wv[CDIM * CDIM], g_wo[CDIM * CDIM];
__device__ __half g_qh[NTOK * CDIM];      // q fp16 (pre-scaled by 0.125)
__device__ __half g_kh[NTOK * CDIM];
__device__ __half g_vh[NTOK * CDIM];
__device__ __half g_xh[NTOK * CDIM];      // attention output fp16
__device__ __half g_mkv[MKV_ELEMS];       // fp16 copy of memory_kv (rna)

__device__ __forceinline__ void mma_f16(float c[4],
    uint32_t a0, uint32_t a1, uint32_t a2, uint32_t a3,
    uint32_t b0, uint32_t b1)
{
    asm volatile(
        "mma.sync.aligned.m16n8k16.row.col.f32.f16.f16.f32 "
        "{%0,%1,%2,%3}, {%4,%5,%6,%7}, {%8,%9}, {%0,%1,%2,%3};"
        : "+f"(c[0]), "+f"(c[1]), "+f"(c[2]), "+f"(c[3])
        : "r"(a0), "r"(a1), "r"(a2), "r"(a3), "r"(b0), "r"(b1));
}

__device__ __forceinline__ void ldsm_x4(uint32_t& r0, uint32_t& r1,
                                        uint32_t& r2, uint32_t& r3, uint32_t addr)
{
    asm volatile("ldmatrix.sync.aligned.m8n8.x4.shared.b16 {%0,%1,%2,%3}, [%4];"
                 : "=r"(r0), "=r"(r1), "=r"(r2), "=r"(r3) : "r"(addr));
}
__device__ __forceinline__ void ldsm_x4_t(uint32_t& r0, uint32_t& r1,
                                          uint32_t& r2, uint32_t& r3, uint32_t addr)
{
    asm volatile("ldmatrix.sync.aligned.m8n8.x4.trans.shared.b16 {%0,%1,%2,%3}, [%4];"
                 : "=r"(r0), "=r"(r1), "=r"(r2), "=r"(r3) : "r"(addr));
}

__device__ __forceinline__ void cp16(uint32_t dst, const void* src, int sz) {
    asm volatile("cp.async.cg.shared.global [%0], [%1], 16, %2;"
                 :: "r"(dst), "l"(src), "r"(sz));
}
__device__ __forceinline__ void cp_commit() {
    asm volatile("cp.async.commit_group;");
}
__device__ __forceinline__ void cp_wait0() { asm volatile("cp.async.wait_group 0;"); }
__device__ __forceinline__ void cp_wait1() { asm volatile("cp.async.wait_group 1;"); }
__device__ __forceinline__ void cp_wait2() { asm volatile("cp.async.wait_group 2;"); }

// ---------------------------------------------------------------------------
// Pre-pass: fp32 -> fp16 (rna), 8 elems per thread. Grid = n / 2048.
// ---------------------------------------------------------------------------
__global__ __launch_bounds__(256) void conv_f16(
    const float* __restrict__ src, __half* __restrict__ dst)
{
    size_t base = ((size_t)blockIdx.x * 256 + threadIdx.x) * 8;
    float4 a = *(const float4*)(src + base);
    float4 b = *(const float4*)(src + base + 4);
    __half2 h0 = __floats2half2_rn(a.x, a.y);
    __half2 h1 = __floats2half2_rn(a.z, a.w);
    __half2 h2 = __floats2half2_rn(b.x, b.y);
    __half2 h3 = __floats2half2_rn(b.z, b.w);
    *(uint4*)(dst + base) = make_uint4(
        *(uint32_t*)&h0, *(uint32_t*)&h1, *(uint32_t*)&h2, *(uint32_t*)&h3);
}

// ---------------------------------------------------------------------------
// FP16-in tensor-core GEMM, 3-stage cp.async pipeline + ldmatrix fragments.
// out[m][n] = sum_k A[m][k] * W[n][k] + bias[n]
// Block tile 128x128, 8 warps (2x4), warp tile 64x32; k-chunk 64 halves.
// Stage = A tile 16KB + W tile 16KB (128 rows x 128B, xor-swizzled 16B chunks:
// phys_chunk = c ^ (row & 7) -> conflict-free cp.async stores AND ldmatrix).
// OM: 0 = fp32 out (final proj), 2 = fp16 out, 3 = fp16 out scaled by 0.125 (q).
// ---------------------------------------------------------------------------
#define GP_STAGE 32768
#define GP_SMEM  (3 * GP_STAGE)   // 98304

template <int OM>
__global__ __launch_bounds__(256) void gemm_h16(
    const __half* __restrict__ A, const __half* __restrict__ W,
    const float* __restrict__ bias, void* __restrict__ outp)
{
    extern __shared__ char sm[];
    const uint32_t sb = (uint32_t)__cvta_generic_to_shared(sm);

    const int tid  = threadIdx.x;
    const int lane = tid & 31;
    const int warp = tid >> 5;
    const int g    = lane >> 2;
    const int tig  = lane & 3;

    const int wm = (warp >> 2) * 64;
    const int wn = (warp & 3) * 32;
    const int m0 = blockIdx.y << 7;
    const int o0 = blockIdx.x << 7;

    float c[4][4][4];
    #pragma unroll
    for (int mi = 0; mi < 4; mi++)
        #pragma unroll
        for (int ni = 0; ni < 4; ni++)
            #pragma unroll
            for (int r = 0; r < 4; r++) c[mi][ni][r] = 0.0f;

    auto issue = [&](int s) {
        const __half* Ab = A + (size_t)m0 * CDIM + s * 64;
        const __half* Wb = W + (size_t)o0 * CDIM + s * 64;
        uint32_t abase = sb + (uint32_t)((s % 3) * GP_STAGE);
        uint32_t bbase = abase + 16384;
        #pragma unroll
        for (int p = 0; p < 4; p++) {
            int i = tid + (p << 8);
            int row = i >> 3, ch = i & 7;
            uint32_t off = (uint32_t)(row * 128 + ((ch ^ (row & 7)) << 4));
            cp16(abase + off, Ab + (size_t)row * CDIM + ch * 8, 16);
            cp16(bbase + off, Wb + (size_t)row * CDIM + ch * 8, 16);
        }
        cp_commit();
    };

    issue(0);
    issue(1);

    for (int s = 0; s < 16; s++) {
        if (s + 2 < 16)      { issue(s + 2); cp_wait2(); }
        else if (s + 1 < 16) { cp_wait1(); }
        else                 { cp_wait0(); }
        __syncthreads();

        const uint32_t ab = sb + (uint32_t)((s % 3) * GP_STAGE);
        const uint32_t bb = ab + 16384;

        #pragma unroll
        for (int ks = 0; ks < 4; ks++) {
            uint32_t a[4][4];
            #pragma unroll
            for (int mi = 0; mi < 4; mi++) {
                int row = wm + (mi << 4) + (lane & 15);
                int ch  = (ks << 1) + (lane >> 4);
                uint32_t addr = ab + (uint32_t)(row * 128 + ((ch ^ (row & 7)) << 4));
                ldsm_x4(a[mi][0], a[mi][1], a[mi][2], a[mi][3], addr);
            }
            uint32_t b[4][2];
            #pragma unroll
            for (int j = 0; j < 2; j++) {
                int q4  = lane >> 3;
                int nil = 2 * j + (q4 >> 1);
                int kh  = q4 & 1;
                int row = wn + (nil << 3) + (lane & 7);
                int ch  = (ks << 1) + kh;
                uint32_t addr = bb + (uint32_t)(row * 128 + ((ch ^ (row & 7)) << 4));
                ldsm_x4(b[2 * j][0], b[2 * j][1], b[2 * j + 1][0], b[2 * j + 1][1], addr);
            }
            #pragma unroll
            for (int mi = 0; mi < 4; mi++)
                #pragma unroll
                for (int ni = 0; ni < 4; ni++)
                    mma_f16(c[mi][ni], a[mi][0], a[mi][1], a[mi][2], a[mi][3],
                            b[ni][0], b[ni][1]);
        }
        __syncthreads();
    }

    #pragma unroll
    for (int mi = 0; mi < 4; mi++) {
        int row = m0 + wm + (mi << 4) + g;
        #pragma unroll
        for (int ni = 0; ni < 4; ni++) {
            int col = o0 + wn + (ni << 3) + (tig << 1);
            float b0 = bias[col], b1 = bias[col + 1];
            float r00 = c[mi][ni][0] + b0, r01 = c[mi][ni][1] + b1;
            float r10 = c[mi][ni][2] + b0, r11 = c[mi][ni][3] + b1;
            if (OM == 3) { r00 *= 0.125f; r01 *= 0.125f; r10 *= 0.125f; r11 *= 0.125f; }
            if (OM == 0) {
                float* out = (float*)outp;
                *(float2*)(out + (size_t)row * CDIM + col) = make_float2(r00, r01);
                *(float2*)(out + (size_t)(row + 8) * CDIM + col) = make_float2(r10, r11);
            } else {
                __half* out = (__half*)outp;
                __half2 h0 = __floats2half2_rn(r00, r01);
                __half2 h1 = __floats2half2_rn(r10, r11);
                *(__half2*)(out + (size_t)row * CDIM + col) = h0;
                *(__half2*)(out + (size_t)(row + 8) * CDIM + col) = h1;
            }
        }
    }
}

// ---------------------------------------------------------------------------
// FP16 tensor-core flash attention (R15 winner core), fp16 q in / fp16 x out.
// Q pre-scaled by 0.125 in its GEMM epilogue; fragments via ldmatrix.
// ---------------------------------------------------------------------------
#define KSTR_H   72                      // halves per K/V/Q smem row (144 B)
#define TILE_B   (64 * KSTR_H * 2)       // 9216 B per tile
#define STAGE_B  (2 * TILE_B)            // 18432 B per stage
#define ATTN_SMEM (2 * STAGE_B)          // 36864 B

__global__ __launch_bounds__(128) void attn_f16_kernel(
    const __half* __restrict__ qh, const __half* __restrict__ kh,
    const __half* __restrict__ vh, const __half* __restrict__ mkv,
    const int* __restrict__ memlen, const int* __restrict__ padv,
    const unsigned char* __restrict__ mask, __half* __restrict__ xout)
{
    extern __shared__ char smc[];
    const uint32_t smem_base = (uint32_t)__cvta_generic_to_shared(smc);

    const int tid  = threadIdx.x;
    const int lane = tid & 31;
    const int warp = tid >> 5;       // 0..3
    const int g    = lane >> 2;      // 0..7
    const int tig  = lane & 3;       // 0..3

    const int s0 = blockIdx.x << 6;
    const int b  = blockIdx.y >> 4;
    const int h  = blockIdx.y & 15;
    const int L  = memlen[b];
    const int P  = padv[b];
    const int Teff = L + P;
    const int qrow0 = warp * 16 + g;

    // ---- Stage Q fp16 (64 rows x 64 halves, stride 72) into buffer 0 ----
    {
        __half* Qst = (__half*)smc;
        for (int i = tid; i < 512; i += 128) {
            int qi = i >> 3;
            int c8 = i & 7;
            *(uint4*)(Qst + qi * KSTR_H + c8 * 8) =
                *(const uint4*)(qh + ((size_t)(s0 + qi) * BATCH + b) * CDIM + h * HCDIM + c8 * 8);
        }
    }
    __syncthreads();

    uint32_t qf[4][4];
    #pragma unroll
    for (int ks = 0; ks < 4; ks++) {
        int row = warp * 16 + (lane & 15);
        int ch  = (ks << 1) + (lane >> 4);
        uint32_t addr = smem_base + (uint32_t)(row * (KSTR_H * 2) + (ch << 4));
        ldsm_x4(qf[ks][0], qf[ks][1], qf[ks][2], qf[ks][3], addr);
    }
    __syncthreads();   // Q staging consumed before gather overwrites buffer 0

    float oacc[8][4];
    #pragma unroll
    for (int ni = 0; ni < 8; ni++)
        #pragma unroll
        for (int r = 0; r < 4; r++) oacc[ni][r] = 0.0f;
    float mrow[2] = { -INFINITY, -INFINITY };
    float lrow[2] = { 0.0f, 0.0f };

    const int ntile = (Teff + 63) >> 6;

    auto gather = [&](int kt) {
        const int t0 = kt << 6;
        const uint32_t kbase = smem_base + (uint32_t)((kt & 1) * STAGE_B);
        const uint32_t vbase = kbase + TILE_B;
        for (int i = tid; i < 512; i += 128) {
            int kj = i >> 3;
            int c8 = i & 7;
            int t = t0 + kj;
            const __half* srcK = kh;
            const __half* srcV = vh;
            int sz = 0;
            if (t < L) {
                const __half* bp = mkv + (((size_t)t * BATCH + b) * NHEAD + h) * (2 * HCDIM);
                srcK = bp + c8 * 8;
                srcV = bp + HCDIM + c8 * 8;
                sz = 16;
            } else if (t < Teff) {
                int j = t - L;
                size_t ro = ((size_t)j * BATCH + b) * CDIM + h * HCDIM + c8 * 8;
                srcK = kh + ro;
                srcV = vh + ro;
                sz = 16;
            }
            uint32_t doff = (uint32_t)(kj * (KSTR_H * 2) + c8 * 16);
            cp16(kbase + doff, srcK, sz);
            cp16(vbase + doff, srcV, sz);
        }
        cp_commit();
    };

    if (ntile > 0) gather(0);

    for (int kt = 0; kt < ntile; kt++) {
        const int t0 = kt << 6;
        if (kt + 1 < ntile) { gather(kt + 1); cp_wait1(); }
        else                { cp_wait0(); }
        __syncthreads();

        const uint32_t kb = smem_base + (uint32_t)((kt & 1) * STAGE_B);
        const uint32_t vb = kb + TILE_B;

        // ---- S = Q K^T ----
        float sv[8][4];
        #pragma unroll
        for (int ni = 0; ni < 8; ni++)
            #pragma unroll
            for (int r = 0; r < 4; r++) sv[ni][r] = 0.0f;

        #pragma unroll
        for (int ks = 0; ks < 4; ks++) {
            #pragma unroll
            for (int j = 0; j < 4; j++) {
                int q4 = lane >> 3;
                int ni = 2 * j + (q4 >> 1);
                int khalf = q4 & 1;
                uint32_t addr = kb + (uint32_t)(((ni << 3) + (lane & 7)) * (KSTR_H * 2)
                                                + (ks << 5) + (khalf << 4));
                uint32_t b00, b01, b10, b11;
                ldsm_x4(b00, b01, b10, b11, addr);
                mma_f16(sv[2 * j],     qf[ks][0], qf[ks][1], qf[ks][2], qf[ks][3], b00, b01);
                mma_f16(sv[2 * j + 1], qf[ks][0], qf[ks][1], qf[ks][2], qf[ks][3], b10, b11);
            }
        }

        // ---- Masking (skipped for tiles fully inside memory) ----
        if (t0 + 64 > L) {
            #pragma unroll
            for (int ni = 0; ni < 8; ni++) {
                #pragma unroll
                for (int cc = 0; cc < 2; cc++) {
                    int t = t0 + (ni << 3) + (tig << 1) + cc;
                    if (t >= Teff) {
                        sv[ni][cc] = -INFINITY;
                        sv[ni][2 + cc] = -INFINITY;
                    } else if (t >= L) {
                        int jn = t - L;
                        int r0 = s0 + qrow0;
                        if (mask[((size_t)r0 * QS + jn) * BATCH + b]) sv[ni][cc] = -INFINITY;
                        if (mask[((size_t)(r0 + 8) * QS + jn) * BATCH + b]) sv[ni][2 + cc] = -INFINITY;
                    }
                }
            }
        }

        // ---- Online softmax per row-half ----
        #pragma unroll
        for (int half = 0; half < 2; half++) {
            const int o0i = half << 1;
            float rm = -INFINITY;
            #pragma unroll
            for (int ni = 0; ni < 8; ni++)
                rm = fmaxf(rm, fmaxf(sv[ni][o0i], sv[ni][o0i + 1]));
            rm = fmaxf(rm, __shfl_xor_sync(0xffffffffu, rm, 1));
            rm = fmaxf(rm, __shfl_xor_sync(0xffffffffu, rm, 2));
            float mn = fmaxf(mrow[half], rm);
            float factor = (mn == -INFINITY) ? 1.0f : __expf(mrow[half] - mn);
            float rs = 0.0f;
            #pragma unroll
            for (int ni = 0; ni < 8; ni++) {
                #pragma unroll
                for (int cc = 0; cc < 2; cc++) {
                    float p = (mn == -INFINITY) ? 0.0f : __expf(sv[ni][o0i + cc] - mn);
                    sv[ni][o0i + cc] = p;
                    rs += p;
                }
            }
            rs += __shfl_xor_sync(0xffffffffu, rs, 1);
            rs += __shfl_xor_sync(0xffffffffu, rs, 2);
            lrow[half] = lrow[half] * factor + rs;
            mrow[half] = mn;
            #pragma unroll
            for (int ni = 0; ni < 8; ni++) {
                oacc[ni][o0i] *= factor;
                oacc[ni][o0i + 1] *= factor;
            }
        }

        // ---- P A-frags: direct pack from C-frags ----
        uint32_t pa[4][4];
        #pragma unroll
        for (int ks = 0; ks < 4; ks++) {
            __half2 p0 = __floats2half2_rn(sv[2*ks][0],     sv[2*ks][1]);
            __half2 p1 = __floats2half2_rn(sv[2*ks][2],     sv[2*ks][3]);
            __half2 p2 = __floats2half2_rn(sv[2*ks + 1][0], sv[2*ks + 1][1]);
            __half2 p3 = __floats2half2_rn(sv[2*ks + 1][2], sv[2*ks + 1][3]);
            pa[ks][0] = *(uint32_t*)&p0;
            pa[ks][1] = *(uint32_t*)&p1;
            pa[ks][2] = *(uint32_t*)&p2;
            pa[ks][3] = *(uint32_t*)&p3;
        }

        // ---- O += P V ----
        #pragma unroll
        for (int ni = 0; ni < 8; ni++) {
            #pragma unroll
            for (int p = 0; p < 2; p++) {
                int q4 = lane >> 3;
                int ksl = 2 * p + (q4 >> 1);
                int tb  = q4 & 1;
                int t   = (ksl << 4) + (tb << 3) + (lane & 7);
                uint32_t addr = vb + (uint32_t)(t * (KSTR_H * 2) + (ni << 4));
                uint32_t v00, v01, v10, v11;
                ldsm_x4_t(v00, v01, v10, v11, addr);
                mma_f16(oacc[ni], pa[2*p][0],   pa[2*p][1],   pa[2*p][2],   pa[2*p][3],   v00, v01);
                mma_f16(oacc[ni], pa[2*p+1][0], pa[2*p+1][1], pa[2*p+1][2], pa[2*p+1][3], v10, v11);
            }
        }
        __syncthreads();
    }

    // ---- Normalize, write x fp16 [s][b][c] (all-masked rows -> 0) ----
    #pragma unroll
    for (int half = 0; half < 2; half++) {
        float inv = (lrow[half] > 0.0f) ? 1.0f / lrow[half] : 0.0f;
        int row = s0 + qrow0 + (half << 3);
        __half* orow = xout + ((size_t)row * BATCH + b) * CDIM + h * HCDIM;
        #pragma unroll
        for (int ni = 0; ni < 8; ni++) {
            int col = (ni << 3) + (tig << 1);
            __half2 hv = __floats2half2_rn(oacc[ni][(half << 1)] * inv,
                                           oacc[ni][(half << 1) + 1] * inv);
            *(__half2*)(orow + col) = hv;
        }
    }
}

// ---------------------------------------------------------------------------
// Launch
// ---------------------------------------------------------------------------
extern "C" void kernel_launch(void* const* d_in, const int* in_sizes, int n_in,
                              void* d_out, int out_size)
{
    const float*         xq     = (const float*)d_in[0];
    const int*           pad    = (const int*)d_in[1];
    const unsigned char* mask   = (const unsigned char*)d_in[2];
    const int*           memlen = (const int*)d_in[3];
    const float*         memkv  = (const float*)d_in[4];
    const float* Wq = (const float*)d_in[5];  const float* bq = (const float*)d_in[6];
    const float* Wk = (const float*)d_in[7];  const float* bk = (const float*)d_in[8];
    const float* Wv = (const float*)d_in[9];  const float* bv = (const float*)d_in[10];
    const float* Wo = (const float*)d_in[11]; const float* bo = (const float*)d_in[12];
    float* out = (float*)d_out;

    __half *xqh, *wq, *wk, *wv, *wo, *qh, *khp, *vhp, *xh, *mkvh;
    cudaGetSymbolAddress((void**)&xqh, g_xqh);
    cudaGetSymbolAddress((void**)&wq,  g_wq);
    cudaGetSymbolAddress((void**)&wk,  g_wk);
    cudaGetSymbolAddress((void**)&wv,  g_wv);
    cudaGetSymbolAddress((void**)&wo,  g_wo);
    cudaGetSymbolAddress((void**)&qh,  g_qh);
    cudaGetSymbolAddress((void**)&khp, g_kh);
    cudaGetSymbolAddress((void**)&vhp, g_vh);
    cudaGetSymbolAddress((void**)&xh,  g_xh);
    cudaGetSymbolAddress((void**)&mkvh, g_mkv);

    // fp32 -> fp16 pre-passes (each conversion replaces one the consumers did)
    conv_f16<<<MKV_ELEMS / 2048, 256>>>(memkv, mkvh);
    conv_f16<<<(NTOK * CDIM) / 2048, 256>>>(xq, xqh);
    conv_f16<<<(CDIM * CDIM) / 2048, 256>>>(Wq, wq);
    conv_f16<<<(CDIM * CDIM) / 2048, 256>>>(Wk, wk);
    conv_f16<<<(CDIM * CDIM) / 2048, 256>>>(Wv, wv);
    conv_f16<<<(CDIM * CDIM) / 2048, 256>>>(Wo, wo);

    cudaFuncSetAttribute(gemm_h16<0>, cudaFuncAttributeMaxDynamicSharedMemorySize, GP_SMEM);
    cudaFuncSetAttribute(gemm_h16<2>, cudaFuncAttributeMaxDynamicSharedMemorySize, GP_SMEM);
    cudaFuncSetAttribute(gemm_h16<3>, cudaFuncAttributeMaxDynamicSharedMemorySize, GP_SMEM);

    dim3 gg(CDIM / 128, NTOK / 128);  // (8, 32)
    gemm_h16<3><<<gg, 256, GP_SMEM>>>(xqh, wq, bq, qh);   // q: fp16, x0.125
    gemm_h16<2><<<gg, 256, GP_SMEM>>>(xqh, wk, bk, khp);  // k: fp16
    gemm_h16<2><<<gg, 256, GP_SMEM>>>(xqh, wv, bv, vhp);  // v: fp16

    cudaFuncSetAttribute(attn_f16_kernel, cudaFuncAttributeMaxDynamicSharedMemorySize, ATTN_SMEM);
    attn_f16_kernel<<<dim3(QS / 64, BATCH * NHEAD), 128, ATTN_SMEM>>>(
        qh, khp, vhp, mkvh, memlen, pad, mask, xh);

    gemm_h16<0><<<gg, 256, GP_SMEM>>>(xh, wo, bo, out);   // out proj: fp32
}